// round 3
// baseline (speedup 1.0000x reference)
#include <cuda_runtime.h>

#define Nn   100000
#define Ee   1600000
#define HIDD 128
#define HEADS 4
#define CH   32
#define LL   2
#define GG   64
#define NCHUNK ((Nn + 255) / 256)   // 391

// ---------------- scratch (static device globals; no allocation) -----------
__device__ __align__(16) float    g_h[Nn*HIDD];
__device__ __align__(16) float    g_xs[Nn*HIDD];
__device__ __align__(16) float    g_as[Nn*HEADS];
__device__ __align__(16) float    g_ad[Nn*HEADS];
__device__ __align__(16) float    g_uv[2*LL*HEADS];
__device__ __align__(16) float    g_pooled[GG*HIDD];
__device__           float        g_cnt[GG];
__device__ __align__(16) float    g_z[GG*64];
// CSR by destination
__device__ __align__(16) int      g_deg[Nn];
__device__ __align__(16) int      g_row[Nn + 1];
__device__ __align__(16) int      g_cur[Nn];
__device__ __align__(16) int      g_bsum[NCHUNK];
__device__ __align__(16) int      g_boff[NCHUNK];
__device__ __align__(16) int      g_srcs[Ee];
__device__ __align__(16) float    g_eas[Ee];

// ---------------- node encoder: h = x * enc_w + enc_b ; zero degree --------
__global__ void k_enc(const float* __restrict__ x, const float* __restrict__ ew,
                      const float* __restrict__ eb) {
    int i = blockIdx.x * blockDim.x + threadIdx.x;
    if (i < Nn) g_deg[i] = 0;
    if (i >= Nn * HIDD) return;
    int n = i >> 7, c = i & 127;
    g_h[i] = x[n] * ew[c] + eb[c];
}

// ---------------- precompute a_e coefficients u,v (rank-1 edge path) -------
__global__ void k_uv(const float* __restrict__ eenc_w, const float* __restrict__ eenc_b,
                     const float* __restrict__ lew, const float* __restrict__ att_e) {
    int tid = threadIdx.x;                 // 256 = L*H*C
    int l = tid >> 7, h = (tid >> 5) & 3, c = tid & 31;
    const float* W = lew + l * HIDD * HIDD;
    int col = h * CH + c;
    float wc = 0.f, bc = 0.f;
    for (int k = 0; k < HIDD; k++) {
        float w = W[k * HIDD + col];
        wc += eenc_w[k] * w;
        bc += eenc_b[k] * w;
    }
    float ae = att_e[l * HEADS * CH + h * CH + c];
    float uu = wc * ae, vv = bc * ae;
    for (int off = 16; off; off >>= 1) {
        uu += __shfl_down_sync(0xffffffffu, uu, off);
        vv += __shfl_down_sync(0xffffffffu, vv, off);
    }
    if (c == 0) {
        g_uv[l * HEADS + h] = uu;
        g_uv[LL * HEADS + l * HEADS + h] = vv;
    }
}

// ---------------- CSR build -------------------------------------------------
__global__ void k_hist(const int* __restrict__ ei) {
    int e = blockIdx.x * blockDim.x + threadIdx.x;
    if (e >= Ee) return;
    atomicAdd(&g_deg[ei[Ee + e]], 1);
}

__global__ void k_scan1() {
    __shared__ int sd[256];
    int t = threadIdx.x;
    int i = blockIdx.x * 256 + t;
    int v = (i < Nn) ? g_deg[i] : 0;
    sd[t] = v;
    __syncthreads();
    for (int off = 1; off < 256; off <<= 1) {
        int x = (t >= off) ? sd[t - off] : 0;
        __syncthreads();
        sd[t] += x;
        __syncthreads();
    }
    if (i < Nn) g_row[i] = sd[t] - v;          // exclusive within chunk
    if (t == 255) g_bsum[blockIdx.x] = sd[255];
}

__global__ void k_scan2() {
    if (threadIdx.x == 0) {
        int run = 0;
        for (int b = 0; b < NCHUNK; b++) { g_boff[b] = run; run += g_bsum[b]; }
    }
}

__global__ void k_scan3() {
    int i = blockIdx.x * blockDim.x + threadIdx.x;
    if (i == 0) g_row[Nn] = Ee;
    if (i >= Nn) return;
    int r = g_row[i] + g_boff[i >> 8];
    g_row[i] = r;
    g_cur[i] = r;
}

__global__ void k_scatter(const int* __restrict__ ei, const float* __restrict__ ea) {
    int e = blockIdx.x * blockDim.x + threadIdx.x;
    if (e >= Ee) return;
    int d = ei[Ee + e];
    int pos = atomicAdd(&g_cur[d], 1);
    g_srcs[pos] = ei[e];
    g_eas[pos] = ea[e];
}

// ---------------- xs = h @ W  (128x128 tile, 8x8/thread) + a_s/a_d epilogue
__global__ void __launch_bounds__(256) k_gemm(const float* __restrict__ W,
                      const float* __restrict__ att_src,
                      const float* __restrict__ att_dst, int l) {
    __shared__ float Ws[32][128];
    __shared__ float As[128][33];
    int tid = threadIdx.x;         // 256
    int tx = tid & 15, ty = tid >> 4;       // cols tx*8, rows ty*8
    int br = blockIdx.x * 128;
    float acc[8][8];
#pragma unroll
    for (int r = 0; r < 8; r++)
#pragma unroll
        for (int c = 0; c < 8; c++) acc[r][c] = 0.f;

    for (int kt = 0; kt < 4; kt++) {
        // stage W tile [32][128]  (1024 float4, 4 per thread)
#pragma unroll
        for (int q = 0; q < 4; q++) {
            int f = tid + q * 256;
            int row = f >> 5, col = (f & 31) * 4;
            *(float4*)&Ws[row][col] = *(const float4*)&W[(kt * 32 + row) * HIDD + col];
        }
        // stage A tile [128][32] -> As padded (coalesced loads, scalar stores)
#pragma unroll
        for (int q = 0; q < 4; q++) {
            int f = tid + q * 256;
            int row = f >> 3, c4 = (f & 7) * 4;
            int gr = br + row;
            float4 a4 = make_float4(0.f, 0.f, 0.f, 0.f);
            if (gr < Nn) a4 = *(const float4*)&g_h[gr * HIDD + kt * 32 + c4];
            As[row][c4 + 0] = a4.x;
            As[row][c4 + 1] = a4.y;
            As[row][c4 + 2] = a4.z;
            As[row][c4 + 3] = a4.w;
        }
        __syncthreads();
#pragma unroll
        for (int k = 0; k < 32; k++) {
            float4 b0 = *(float4*)&Ws[k][tx * 8];
            float4 b1 = *(float4*)&Ws[k][tx * 8 + 4];
            float a[8];
#pragma unroll
            for (int r = 0; r < 8; r++) a[r] = As[ty * 8 + r][k];
#pragma unroll
            for (int r = 0; r < 8; r++) {
                acc[r][0] += a[r] * b0.x; acc[r][1] += a[r] * b0.y;
                acc[r][2] += a[r] * b0.z; acc[r][3] += a[r] * b0.w;
                acc[r][4] += a[r] * b1.x; acc[r][5] += a[r] * b1.y;
                acc[r][6] += a[r] * b1.z; acc[r][7] += a[r] * b1.w;
            }
        }
        __syncthreads();
    }

    // store xs
#pragma unroll
    for (int r = 0; r < 8; r++) {
        int gr = br + ty * 8 + r;
        if (gr < Nn) {
            float4 o0 = make_float4(acc[r][0], acc[r][1], acc[r][2], acc[r][3]);
            float4 o1 = make_float4(acc[r][4], acc[r][5], acc[r][6], acc[r][7]);
            *(float4*)&g_xs[gr * HIDD + tx * 8] = o0;
            *(float4*)&g_xs[gr * HIDD + tx * 8 + 4] = o1;
        }
    }

    // fused attention logits: a_s[n,h], a_d[n,h]
    // thread cols tx*8..tx*8+7 all lie in head h = tx>>2
    int h = tx >> 2;
    float sv[8], dv[8];
#pragma unroll
    for (int j = 0; j < 8; j++) {
        sv[j] = att_src[l * HIDD + tx * 8 + j];
        dv[j] = att_dst[l * HIDD + tx * 8 + j];
    }
#pragma unroll
    for (int r = 0; r < 8; r++) {
        float ps = 0.f, pd = 0.f;
#pragma unroll
        for (int j = 0; j < 8; j++) { ps += acc[r][j] * sv[j]; pd += acc[r][j] * dv[j]; }
        ps += __shfl_down_sync(0xffffffffu, ps, 2, 4);
        ps += __shfl_down_sync(0xffffffffu, ps, 1, 4);
        pd += __shfl_down_sync(0xffffffffu, pd, 2, 4);
        pd += __shfl_down_sync(0xffffffffu, pd, 1, 4);
        int gr = br + ty * 8 + r;
        if ((tx & 3) == 0 && gr < Nn) {
            g_as[gr * HEADS + h] = ps;
            g_ad[gr * HEADS + h] = pd;
        }
    }
}

// ---------------- fused edge kernel: warp per dst node, online softmax -----
__global__ void __launch_bounds__(256) k_edge(const float* __restrict__ conv_b,
                       const float* __restrict__ gamma, const float* __restrict__ beta,
                       const float* __restrict__ mean, const float* __restrict__ var,
                       int l) {
    int warp = (blockIdx.x * blockDim.x + threadIdx.x) >> 5;
    int lane = threadIdx.x & 31;
    if (warp >= Nn) return;
    const int d = warp;
    const int h = lane >> 3;
    const int r0 = g_row[d], r1 = g_row[d + 1];
    const float base = g_ad[d * HEADS + h] + g_uv[LL * HEADS + l * HEADS + h];
    const float u = g_uv[l * HEADS + h];

    float m = -1e30f, den = 0.f;
    float ac0 = 0.f, ac1 = 0.f, ac2 = 0.f, ac3 = 0.f;

    int e = r0;
    for (; e + 1 < r1; e += 2) {
        int s0 = g_srcs[e], s1 = g_srcs[e + 1];
        float a0 = g_eas[e], a1 = g_eas[e + 1];
        float as0 = g_as[s0 * HEADS + h];
        float as1 = g_as[s1 * HEADS + h];
        float4 X0 = *(const float4*)&g_xs[s0 * HIDD + lane * 4];
        float4 X1 = *(const float4*)&g_xs[s1 * HIDD + lane * 4];
        float al0 = as0 + base + a0 * u;
        float al1 = as1 + base + a1 * u;
        al0 = (al0 > 0.f) ? al0 : 0.2f * al0;
        al1 = (al1 > 0.f) ? al1 : 0.2f * al1;
        float mn = fmaxf(m, fmaxf(al0, al1));
        float f = __expf(m - mn);
        float p0 = __expf(al0 - mn);
        float p1 = __expf(al1 - mn);
        den = den * f + p0 + p1;
        ac0 = ac0 * f + p0 * X0.x + p1 * X1.x;
        ac1 = ac1 * f + p0 * X0.y + p1 * X1.y;
        ac2 = ac2 * f + p0 * X0.z + p1 * X1.z;
        ac3 = ac3 * f + p0 * X0.w + p1 * X1.w;
        m = mn;
    }
    if (e < r1) {
        int s0 = g_srcs[e];
        float a0 = g_eas[e];
        float as0 = g_as[s0 * HEADS + h];
        float4 X0 = *(const float4*)&g_xs[s0 * HIDD + lane * 4];
        float al0 = as0 + base + a0 * u;
        al0 = (al0 > 0.f) ? al0 : 0.2f * al0;
        float mn = fmaxf(m, al0);
        float f = __expf(m - mn);
        float p0 = __expf(al0 - mn);
        den = den * f + p0;
        ac0 = ac0 * f + p0 * X0.x;
        ac1 = ac1 * f + p0 * X0.y;
        ac2 = ac2 * f + p0 * X0.z;
        ac3 = ac3 * f + p0 * X0.w;
    }
    float scale = 1.f / (den + 1e-16f);

    int cb = l * HIDD + lane * 4;
    float4 cb4 = *(const float4*)&conv_b[cb];
    float4 gm4 = *(const float4*)&gamma[cb];
    float4 bt4 = *(const float4*)&beta[cb];
    float4 mn4 = *(const float4*)&mean[cb];
    float4 vr4 = *(const float4*)&var[cb];
    float4 hv = *(const float4*)&g_h[d * HIDD + lane * 4];
    float o0 = (ac0 * scale + cb4.x - mn4.x) * rsqrtf(vr4.x + 1e-5f) * gm4.x + bt4.x;
    float o1 = (ac1 * scale + cb4.y - mn4.y) * rsqrtf(vr4.y + 1e-5f) * gm4.y + bt4.y;
    float o2 = (ac2 * scale + cb4.z - mn4.z) * rsqrtf(vr4.z + 1e-5f) * gm4.z + bt4.z;
    float o3 = (ac3 * scale + cb4.w - mn4.w) * rsqrtf(vr4.w + 1e-5f) * gm4.w + bt4.w;
    hv.x += fmaxf(o0, 0.f);
    hv.y += fmaxf(o1, 0.f);
    hv.z += fmaxf(o2, 0.f);
    hv.w += fmaxf(o3, 0.f);
    *(float4*)&g_h[d * HIDD + lane * 4] = hv;
}

// ---------------- pooling ---------------------------------------------------
__global__ void k_zeropool() {
    int i = blockIdx.x * blockDim.x + threadIdx.x;
    if (i < GG * HIDD) g_pooled[i] = 0.f;
    if (i < GG) g_cnt[i] = 0.f;
}

#define NPB 256
__global__ void k_pool(const int* __restrict__ batch) {
    int c = threadIdx.x;              // 128 channels
    int n0 = blockIdx.x * NPB;
    int n1 = min(n0 + NPB, Nn);
    int cur = -1; float s = 0.f; float cn = 0.f;
    for (int n = n0; n < n1; n++) {
        int g = batch[n];
        if (g != cur) {
            if (cur >= 0) {
                atomicAdd(&g_pooled[cur * HIDD + c], s);
                if (c == 0) atomicAdd(&g_cnt[cur], cn);
            }
            cur = g; s = 0.f; cn = 0.f;
        }
        s += g_h[n * HIDD + c];
        cn += 1.f;
    }
    if (cur >= 0) {
        atomicAdd(&g_pooled[cur * HIDD + c], s);
        if (c == 0) atomicAdd(&g_cnt[cur], cn);
    }
}

// ---------------- classifier head ------------------------------------------
__global__ void k_mlp1(const float* __restrict__ w1, const float* __restrict__ b1) {
    int i = blockIdx.x * blockDim.x + threadIdx.x;   // GG*64
    if (i >= GG * 64) return;
    int g = i >> 6, j = i & 63;
    float cnt = fmaxf(g_cnt[g], 1.f);
    float s = 0.f;
    for (int k = 0; k < HIDD; k++) s += g_pooled[g * HIDD + k] * w1[k * 64 + j];
    g_z[i] = fmaxf(s / cnt + b1[j], 0.f);
}

__global__ void k_mlp2(const float* __restrict__ w2, const float* __restrict__ b2,
                       float* __restrict__ out) {
    int g = threadIdx.x;
    if (g >= GG) return;
    float s = b2[0];
    for (int j = 0; j < 64; j++) s += g_z[g * 64 + j] * w2[j];
    out[g] = 1.f / (1.f + __expf(-s));
}

// ---------------- launch ----------------------------------------------------
extern "C" void kernel_launch(void* const* d_in, const int* in_sizes, int n_in,
                              void* d_out, int out_size) {
    const float* x        = (const float*)d_in[0];
    const float* ea       = (const float*)d_in[1];
    const int*   ei       = (const int*)  d_in[2];
    const int*   batch    = (const int*)  d_in[3];
    const float* enc_w    = (const float*)d_in[4];
    const float* enc_b    = (const float*)d_in[5];
    const float* eenc_w   = (const float*)d_in[6];
    const float* eenc_b   = (const float*)d_in[7];
    const float* lin_w    = (const float*)d_in[8];
    const float* att_src  = (const float*)d_in[9];
    const float* att_dst  = (const float*)d_in[10];
    const float* att_edge = (const float*)d_in[11];
    const float* lin_ew   = (const float*)d_in[12];
    const float* conv_b   = (const float*)d_in[13];
    const float* bn_gamma = (const float*)d_in[14];
    const float* bn_beta  = (const float*)d_in[15];
    const float* bn_mean  = (const float*)d_in[16];
    const float* bn_var   = (const float*)d_in[17];
    const float* w1       = (const float*)d_in[18];
    const float* b1       = (const float*)d_in[19];
    const float* w2       = (const float*)d_in[20];
    const float* b2       = (const float*)d_in[21];
    float* out = (float*)d_out;

    const int TB = 256;
    int gridNH = (Nn * HIDD + TB - 1) / TB;
    int gridE  = (Ee + TB - 1) / TB;
    int gridN  = (Nn + TB - 1) / TB;
    int gridNW = (Nn * 32 + TB - 1) / TB;

    k_enc<<<gridNH, TB>>>(x, enc_w, enc_b);
    k_uv<<<1, 256>>>(eenc_w, eenc_b, lin_ew, att_edge);

    // CSR build (by dst)
    k_hist<<<gridE, TB>>>(ei);
    k_scan1<<<NCHUNK, 256>>>();
    k_scan2<<<1, 32>>>();
    k_scan3<<<gridN, TB>>>();
    k_scatter<<<gridE, TB>>>(ei, ea);

    for (int l = 0; l < LL; l++) {
        k_gemm<<<(Nn + 127) / 128, 256>>>(lin_w + l * HIDD * HIDD, att_src, att_dst, l);
        k_edge<<<gridNW, TB>>>(conv_b, bn_gamma, bn_beta, bn_mean, bn_var, l);
    }

    k_zeropool<<<(GG * HIDD + TB - 1) / TB, TB>>>();
    k_pool<<<(Nn + NPB - 1) / NPB, 128>>>(batch);
    k_mlp1<<<(GG * 64 + TB - 1) / TB, TB>>>(w1, b1);
    k_mlp2<<<1, 64>>>(w2, b2, out);
}

// round 4
// speedup vs baseline: 1.0505x; 1.0505x over previous
#include <cuda_runtime.h>

#define Nn   100000
#define Ee   1600000
#define HIDD 128
#define HEADS 4
#define CH   32
#define LL   2
#define GG   64
#define NCHUNK ((Nn + 255) / 256)   // 391

// ---------------- scratch (static device globals; no allocation) -----------
__device__ __align__(16) float    g_h[Nn*HIDD];
__device__ __align__(16) float    g_xs[Nn*HIDD];
__device__ __align__(16) float    g_as[Nn*HEADS];
__device__ __align__(16) float    g_ad[Nn*HEADS];
__device__ __align__(16) float    g_uv[2*LL*HEADS];
__device__ __align__(16) float    g_pooled[GG*HIDD];
__device__           float        g_cnt[GG];
__device__ __align__(16) float    g_z[GG*64];
// CSR by destination
__device__ __align__(16) int      g_deg[Nn];
__device__ __align__(16) int      g_row[Nn + 1];
__device__ __align__(16) int      g_cur[Nn];
__device__ __align__(16) int      g_bsum[NCHUNK];
__device__ __align__(16) int      g_boff[NCHUNK];
__device__ __align__(16) int      g_srcs[Ee];
__device__ __align__(16) float    g_eas[Ee];

// ---------------- node encoder: h = x * enc_w + enc_b ; zero degree --------
__global__ void k_enc(const float* __restrict__ x, const float* __restrict__ ew,
                      const float* __restrict__ eb) {
    int i = blockIdx.x * blockDim.x + threadIdx.x;
    if (i < Nn) g_deg[i] = 0;
    if (i >= Nn * HIDD) return;
    int n = i >> 7, c = i & 127;
    g_h[i] = x[n] * ew[c] + eb[c];
}

// ---------------- precompute a_e coefficients u,v (rank-1 edge path) -------
__global__ void k_uv(const float* __restrict__ eenc_w, const float* __restrict__ eenc_b,
                     const float* __restrict__ lew, const float* __restrict__ att_e) {
    int tid = threadIdx.x;                 // 256 = L*H*C
    int l = tid >> 7, h = (tid >> 5) & 3, c = tid & 31;
    const float* W = lew + l * HIDD * HIDD;
    int col = h * CH + c;
    float wc = 0.f, bc = 0.f;
    for (int k = 0; k < HIDD; k++) {
        float w = W[k * HIDD + col];
        wc += eenc_w[k] * w;
        bc += eenc_b[k] * w;
    }
    float ae = att_e[l * HEADS * CH + h * CH + c];
    float uu = wc * ae, vv = bc * ae;
    for (int off = 16; off; off >>= 1) {
        uu += __shfl_down_sync(0xffffffffu, uu, off);
        vv += __shfl_down_sync(0xffffffffu, vv, off);
    }
    if (c == 0) {
        g_uv[l * HEADS + h] = uu;
        g_uv[LL * HEADS + l * HEADS + h] = vv;
    }
}

// ---------------- CSR build -------------------------------------------------
__global__ void k_hist(const int* __restrict__ ei) {
    int e = blockIdx.x * blockDim.x + threadIdx.x;
    if (e >= Ee) return;
    atomicAdd(&g_deg[ei[Ee + e]], 1);
}

__global__ void k_scan1() {
    __shared__ int sd[256];
    int t = threadIdx.x;
    int i = blockIdx.x * 256 + t;
    int v = (i < Nn) ? g_deg[i] : 0;
    sd[t] = v;
    __syncthreads();
    for (int off = 1; off < 256; off <<= 1) {
        int x = (t >= off) ? sd[t - off] : 0;
        __syncthreads();
        sd[t] += x;
        __syncthreads();
    }
    if (i < Nn) g_row[i] = sd[t] - v;          // exclusive within chunk
    if (t == 255) g_bsum[blockIdx.x] = sd[255];
}

__global__ void k_scan2() {
    if (threadIdx.x == 0) {
        int run = 0;
        for (int b = 0; b < NCHUNK; b++) { g_boff[b] = run; run += g_bsum[b]; }
    }
}

__global__ void k_scan3() {
    int i = blockIdx.x * blockDim.x + threadIdx.x;
    if (i == 0) g_row[Nn] = Ee;
    if (i >= Nn) return;
    int r = g_row[i] + g_boff[i >> 8];
    g_row[i] = r;
    g_cur[i] = r;
}

__global__ void k_scatter(const int* __restrict__ ei, const float* __restrict__ ea) {
    int e = blockIdx.x * blockDim.x + threadIdx.x;
    if (e >= Ee) return;
    int d = ei[Ee + e];
    int pos = atomicAdd(&g_cur[d], 1);
    g_srcs[pos] = ei[e];
    g_eas[pos] = ea[e];
}

// ---------------- xs = h @ W (64x128 tile) + fused a_s/a_d epilogue --------
__global__ void __launch_bounds__(256) k_gemm(const float* __restrict__ W,
                      const float* __restrict__ att_src,
                      const float* __restrict__ att_dst, int l) {
    __shared__ float Ws[32][128];
    __shared__ float As[64][32];
    int tid = threadIdx.x;         // 256
    int tx = tid & 31, ty = tid >> 5;
    int br = blockIdx.x * 64;
    float acc[8][4];
#pragma unroll
    for (int r = 0; r < 8; r++) { acc[r][0]=acc[r][1]=acc[r][2]=acc[r][3]=0.f; }

    for (int kt = 0; kt < 4; kt++) {
#pragma unroll
        for (int q = 0; q < 4; q++) {
            int f = tid + q * 256;
            int row = f >> 5, col = (f & 31) * 4;
            *(float4*)&Ws[row][col] = *(const float4*)&W[(kt * 32 + row) * HIDD + col];
        }
#pragma unroll
        for (int q = 0; q < 2; q++) {
            int f = tid + q * 256;
            int row = f >> 3, col = (f & 7) * 4;
            int gr = br + row;
            float4 a4 = make_float4(0.f, 0.f, 0.f, 0.f);
            if (gr < Nn) a4 = *(const float4*)&g_h[gr * HIDD + kt * 32 + col];
            *(float4*)&As[row][col] = a4;
        }
        __syncthreads();
#pragma unroll
        for (int k = 0; k < 32; k++) {
            float4 b = *(float4*)&Ws[k][tx * 4];
#pragma unroll
            for (int r = 0; r < 8; r++) {
                float a = As[ty * 8 + r][k];
                acc[r][0] += a * b.x;
                acc[r][1] += a * b.y;
                acc[r][2] += a * b.z;
                acc[r][3] += a * b.w;
            }
        }
        __syncthreads();
    }
#pragma unroll
    for (int r = 0; r < 8; r++) {
        int gr = br + ty * 8 + r;
        if (gr < Nn) {
            float4 o = make_float4(acc[r][0], acc[r][1], acc[r][2], acc[r][3]);
            *(float4*)&g_xs[gr * HIDD + tx * 4] = o;
        }
    }

    // fused attention logits: head h = tx>>3; reduce over the 8 lanes of the head
    int h = tx >> 3;
    float sv[4], dv[4];
#pragma unroll
    for (int j = 0; j < 4; j++) {
        sv[j] = att_src[l * HIDD + tx * 4 + j];
        dv[j] = att_dst[l * HIDD + tx * 4 + j];
    }
#pragma unroll
    for (int r = 0; r < 8; r++) {
        float ps = 0.f, pd = 0.f;
#pragma unroll
        for (int j = 0; j < 4; j++) { ps += acc[r][j] * sv[j]; pd += acc[r][j] * dv[j]; }
#pragma unroll
        for (int o = 4; o; o >>= 1) {
            ps += __shfl_down_sync(0xffffffffu, ps, o, 8);
            pd += __shfl_down_sync(0xffffffffu, pd, o, 8);
        }
        int gr = br + ty * 8 + r;
        if ((tx & 7) == 0 && gr < Nn) {
            g_as[gr * HEADS + h] = ps;
            g_ad[gr * HEADS + h] = pd;
        }
    }
}

// ---------------- fused edge kernel: warp per dst, single pass, no max -----
__global__ void __launch_bounds__(256) k_edge(const float* __restrict__ conv_b,
                       const float* __restrict__ gamma, const float* __restrict__ beta,
                       const float* __restrict__ mean, const float* __restrict__ var,
                       int l) {
    int warp = (blockIdx.x * blockDim.x + threadIdx.x) >> 5;
    int lane = threadIdx.x & 31;
    if (warp >= Nn) return;
    const int d = warp;
    const int h = lane >> 3;
    const int r0 = g_row[d], r1 = g_row[d + 1];
    const float base = g_ad[d * HEADS + h] + g_uv[LL * HEADS + l * HEADS + h];
    const float u = g_uv[l * HEADS + h];

    float den = 0.f;
    float ac0 = 0.f, ac1 = 0.f, ac2 = 0.f, ac3 = 0.f;

    int e = r0;
    for (; e + 3 < r1; e += 4) {
        int s0 = g_srcs[e],     s1 = g_srcs[e + 1];
        int s2 = g_srcs[e + 2], s3 = g_srcs[e + 3];
        float a0 = g_eas[e],     a1 = g_eas[e + 1];
        float a2 = g_eas[e + 2], a3 = g_eas[e + 3];
        float as0 = g_as[s0 * HEADS + h];
        float as1 = g_as[s1 * HEADS + h];
        float as2 = g_as[s2 * HEADS + h];
        float as3 = g_as[s3 * HEADS + h];
        float4 X0 = *(const float4*)&g_xs[s0 * HIDD + lane * 4];
        float4 X1 = *(const float4*)&g_xs[s1 * HIDD + lane * 4];
        float4 X2 = *(const float4*)&g_xs[s2 * HIDD + lane * 4];
        float4 X3 = *(const float4*)&g_xs[s3 * HIDD + lane * 4];
        float al0 = as0 + base + a0 * u;
        float al1 = as1 + base + a1 * u;
        float al2 = as2 + base + a2 * u;
        float al3 = as3 + base + a3 * u;
        al0 = (al0 > 0.f) ? al0 : 0.2f * al0;
        al1 = (al1 > 0.f) ? al1 : 0.2f * al1;
        al2 = (al2 > 0.f) ? al2 : 0.2f * al2;
        al3 = (al3 > 0.f) ? al3 : 0.2f * al3;
        float p0 = __expf(al0);
        float p1 = __expf(al1);
        float p2 = __expf(al2);
        float p3 = __expf(al3);
        den += (p0 + p1) + (p2 + p3);
        ac0 += p0 * X0.x + p1 * X1.x + p2 * X2.x + p3 * X3.x;
        ac1 += p0 * X0.y + p1 * X1.y + p2 * X2.y + p3 * X3.y;
        ac2 += p0 * X0.z + p1 * X1.z + p2 * X2.z + p3 * X3.z;
        ac3 += p0 * X0.w + p1 * X1.w + p2 * X2.w + p3 * X3.w;
    }
    for (; e < r1; e++) {
        int s0 = g_srcs[e];
        float a0 = g_eas[e];
        float as0 = g_as[s0 * HEADS + h];
        float4 X0 = *(const float4*)&g_xs[s0 * HIDD + lane * 4];
        float al0 = as0 + base + a0 * u;
        al0 = (al0 > 0.f) ? al0 : 0.2f * al0;
        float p0 = __expf(al0);
        den += p0;
        ac0 += p0 * X0.x;
        ac1 += p0 * X0.y;
        ac2 += p0 * X0.z;
        ac3 += p0 * X0.w;
    }
    float scale = 1.f / (den + 1e-16f);

    int cb = l * HIDD + lane * 4;
    float4 cb4 = *(const float4*)&conv_b[cb];
    float4 gm4 = *(const float4*)&gamma[cb];
    float4 bt4 = *(const float4*)&beta[cb];
    float4 mn4 = *(const float4*)&mean[cb];
    float4 vr4 = *(const float4*)&var[cb];
    float4 hv = *(const float4*)&g_h[d * HIDD + lane * 4];
    float o0 = (ac0 * scale + cb4.x - mn4.x) * rsqrtf(vr4.x + 1e-5f) * gm4.x + bt4.x;
    float o1 = (ac1 * scale + cb4.y - mn4.y) * rsqrtf(vr4.y + 1e-5f) * gm4.y + bt4.y;
    float o2 = (ac2 * scale + cb4.z - mn4.z) * rsqrtf(vr4.z + 1e-5f) * gm4.z + bt4.z;
    float o3 = (ac3 * scale + cb4.w - mn4.w) * rsqrtf(vr4.w + 1e-5f) * gm4.w + bt4.w;
    hv.x += fmaxf(o0, 0.f);
    hv.y += fmaxf(o1, 0.f);
    hv.z += fmaxf(o2, 0.f);
    hv.w += fmaxf(o3, 0.f);
    *(float4*)&g_h[d * HIDD + lane * 4] = hv;
}

// ---------------- pooling ---------------------------------------------------
__global__ void k_zeropool() {
    int i = blockIdx.x * blockDim.x + threadIdx.x;
    if (i < GG * HIDD) g_pooled[i] = 0.f;
    if (i < GG) g_cnt[i] = 0.f;
}

#define NPB 256
__global__ void k_pool(const int* __restrict__ batch) {
    int c = threadIdx.x;              // 128 channels
    int n0 = blockIdx.x * NPB;
    int n1 = min(n0 + NPB, Nn);
    int cur = -1; float s = 0.f; float cn = 0.f;
    for (int n = n0; n < n1; n++) {
        int g = batch[n];
        if (g != cur) {
            if (cur >= 0) {
                atomicAdd(&g_pooled[cur * HIDD + c], s);
                if (c == 0) atomicAdd(&g_cnt[cur], cn);
            }
            cur = g; s = 0.f; cn = 0.f;
        }
        s += g_h[n * HIDD + c];
        cn += 1.f;
    }
    if (cur >= 0) {
        atomicAdd(&g_pooled[cur * HIDD + c], s);
        if (c == 0) atomicAdd(&g_cnt[cur], cn);
    }
}

// ---------------- classifier head ------------------------------------------
__global__ void k_mlp1(const float* __restrict__ w1, const float* __restrict__ b1) {
    int i = blockIdx.x * blockDim.x + threadIdx.x;   // GG*64
    if (i >= GG * 64) return;
    int g = i >> 6, j = i & 63;
    float cnt = fmaxf(g_cnt[g], 1.f);
    float s = 0.f;
    for (int k = 0; k < HIDD; k++) s += g_pooled[g * HIDD + k] * w1[k * 64 + j];
    g_z[i] = fmaxf(s / cnt + b1[j], 0.f);
}

__global__ void k_mlp2(const float* __restrict__ w2, const float* __restrict__ b2,
                       float* __restrict__ out) {
    int g = threadIdx.x;
    if (g >= GG) return;
    float s = b2[0];
    for (int j = 0; j < 64; j++) s += g_z[g * 64 + j] * w2[j];
    out[g] = 1.f / (1.f + __expf(-s));
}

// ---------------- launch ----------------------------------------------------
extern "C" void kernel_launch(void* const* d_in, const int* in_sizes, int n_in,
                              void* d_out, int out_size) {
    const float* x        = (const float*)d_in[0];
    const float* ea       = (const float*)d_in[1];
    const int*   ei       = (const int*)  d_in[2];
    const int*   batch    = (const int*)  d_in[3];
    const float* enc_w    = (const float*)d_in[4];
    const float* enc_b    = (const float*)d_in[5];
    const float* eenc_w   = (const float*)d_in[6];
    const float* eenc_b   = (const float*)d_in[7];
    const float* lin_w    = (const float*)d_in[8];
    const float* att_src  = (const float*)d_in[9];
    const float* att_dst  = (const float*)d_in[10];
    const float* att_edge = (const float*)d_in[11];
    const float* lin_ew   = (const float*)d_in[12];
    const float* conv_b   = (const float*)d_in[13];
    const float* bn_gamma = (const float*)d_in[14];
    const float* bn_beta  = (const float*)d_in[15];
    const float* bn_mean  = (const float*)d_in[16];
    const float* bn_var   = (const float*)d_in[17];
    const float* w1       = (const float*)d_in[18];
    const float* b1       = (const float*)d_in[19];
    const float* w2       = (const float*)d_in[20];
    const float* b2       = (const float*)d_in[21];
    float* out = (float*)d_out;

    const int TB = 256;
    int gridNH = (Nn * HIDD + TB - 1) / TB;
    int gridE  = (Ee + TB - 1) / TB;
    int gridN  = (Nn + TB - 1) / TB;
    int gridNW = (Nn * 32 + TB - 1) / TB;

    k_enc<<<gridNH, TB>>>(x, enc_w, enc_b);
    k_uv<<<1, 256>>>(eenc_w, eenc_b, lin_ew, att_edge);

    // CSR build (by dst)
    k_hist<<<gridE, TB>>>(ei);
    k_scan1<<<NCHUNK, 256>>>();
    k_scan2<<<1, 32>>>();
    k_scan3<<<gridN, TB>>>();
    k_scatter<<<gridE, TB>>>(ei, ea);

    for (int l = 0; l < LL; l++) {
        k_gemm<<<(Nn + 63) / 64, 256>>>(lin_w + l * HIDD * HIDD, att_src, att_dst, l);
        k_edge<<<gridNW, TB>>>(conv_b, bn_gamma, bn_beta, bn_mean, bn_var, l);
    }

    k_zeropool<<<(GG * HIDD + TB - 1) / TB, TB>>>();
    k_pool<<<(Nn + NPB - 1) / NPB, 128>>>(batch);
    k_mlp1<<<(GG * 64 + TB - 1) / TB, TB>>>(w1, b1);
    k_mlp2<<<1, 64>>>(w2, b2, out);
}

// round 5
// speedup vs baseline: 1.0959x; 1.0432x over previous
#include <cuda_runtime.h>

#define Nn   100000
#define Ee   1600000
#define HIDD 128
#define HEADS 4
#define CH   32
#define LL   2
#define GG   64
#define NCHUNK ((Nn + 255) / 256)   // 391

// ---------------- scratch (static device globals; no allocation) -----------
__device__ __align__(16) float    g_h[Nn*HIDD];
__device__ __align__(16) float    g_xs[Nn*HIDD];
__device__ __align__(16) float    g_as[Nn*HEADS];
__device__ __align__(16) float    g_ad[Nn*HEADS];
__device__ __align__(16) float    g_uv[2*LL*HEADS];
__device__ __align__(16) float    g_pooled[GG*HIDD];
__device__           float        g_cnt[GG];
__device__ __align__(16) float    g_z[GG*64];
// CSR by destination
__device__ __align__(16) int      g_deg[Nn];
__device__ __align__(16) int      g_row[Nn + 1];
__device__ __align__(16) int      g_cur[Nn];
__device__ __align__(16) int      g_bsum[NCHUNK];
__device__ __align__(16) int      g_boff[NCHUNK];
__device__ __align__(16) int2     g_pack[Ee];      // (src, ea bits)

__device__ __forceinline__ float to_tf32(float x) {
    unsigned u;
    asm("cvt.rna.tf32.f32 %0, %1;" : "=r"(u) : "f"(x));
    return __uint_as_float(u);
}

// ---------------- node encoder: h = x * enc_w + enc_b ; zero degree --------
__global__ void k_enc(const float* __restrict__ x, const float* __restrict__ ew,
                      const float* __restrict__ eb) {
    int i = blockIdx.x * blockDim.x + threadIdx.x;
    if (i < Nn) g_deg[i] = 0;
    if (i >= Nn * HIDD) return;
    int n = i >> 7, c = i & 127;
    g_h[i] = x[n] * ew[c] + eb[c];
}

// ---------------- precompute a_e coefficients u,v (rank-1 edge path) -------
__global__ void k_uv(const float* __restrict__ eenc_w, const float* __restrict__ eenc_b,
                     const float* __restrict__ lew, const float* __restrict__ att_e) {
    int tid = threadIdx.x;                 // 256 = L*H*C
    int l = tid >> 7, h = (tid >> 5) & 3, c = tid & 31;
    const float* W = lew + l * HIDD * HIDD;
    int col = h * CH + c;
    float wc = 0.f, bc = 0.f;
    for (int k = 0; k < HIDD; k++) {
        float w = W[k * HIDD + col];
        wc += eenc_w[k] * w;
        bc += eenc_b[k] * w;
    }
    float ae = att_e[l * HEADS * CH + h * CH + c];
    float uu = wc * ae, vv = bc * ae;
    for (int off = 16; off; off >>= 1) {
        uu += __shfl_down_sync(0xffffffffu, uu, off);
        vv += __shfl_down_sync(0xffffffffu, vv, off);
    }
    if (c == 0) {
        g_uv[l * HEADS + h] = uu;
        g_uv[LL * HEADS + l * HEADS + h] = vv;
    }
}

// ---------------- CSR build -------------------------------------------------
__global__ void k_hist(const int* __restrict__ ei) {
    int e = blockIdx.x * blockDim.x + threadIdx.x;
    if (e >= Ee) return;
    atomicAdd(&g_deg[ei[Ee + e]], 1);
}

__global__ void k_scan1() {
    __shared__ int sd[256];
    int t = threadIdx.x;
    int i = blockIdx.x * 256 + t;
    int v = (i < Nn) ? g_deg[i] : 0;
    sd[t] = v;
    __syncthreads();
    for (int off = 1; off < 256; off <<= 1) {
        int x = (t >= off) ? sd[t - off] : 0;
        __syncthreads();
        sd[t] += x;
        __syncthreads();
    }
    if (i < Nn) g_row[i] = sd[t] - v;          // exclusive within chunk
    if (t == 255) g_bsum[blockIdx.x] = sd[255];
}

__global__ void k_scan2() {
    if (threadIdx.x == 0) {
        int run = 0;
        for (int b = 0; b < NCHUNK; b++) { g_boff[b] = run; run += g_bsum[b]; }
    }
}

__global__ void k_scan3() {
    int i = blockIdx.x * blockDim.x + threadIdx.x;
    if (i == 0) g_row[Nn] = Ee;
    if (i >= Nn) return;
    int r = g_row[i] + g_boff[i >> 8];
    g_row[i] = r;
    g_cur[i] = r;
}

__global__ void k_scatter(const int* __restrict__ ei, const float* __restrict__ ea) {
    int e = blockIdx.x * blockDim.x + threadIdx.x;
    if (e >= Ee) return;
    int d = ei[Ee + e];
    int pos = atomicAdd(&g_cur[d], 1);
    g_pack[pos] = make_int2(ei[e], __float_as_int(ea[e]));
}

// ---------------- xs = h @ W  via tf32 mma.sync (128-row CTA) --------------
// 8 warps x 16 rows; full N=128 in accumulators; K staged 32 per iteration.
__global__ void __launch_bounds__(256) k_gemm(const float* __restrict__ W,
                      const float* __restrict__ att_src,
                      const float* __restrict__ att_dst, int l) {
    __shared__ float As[128][36];     // [row][k]   pad 36: conflict-free frag loads
    __shared__ float Ws[32][132];     // [k][col]   pad 132: conflict-free frag loads
    int tid = threadIdx.x;
    int warp = tid >> 5, lane = tid & 31;
    int g = lane >> 2, t = lane & 3;
    int br = blockIdx.x * 128;
    int r0 = warp * 16 + g;           // fragment row (and r0+8)

    float acc[16][4];
#pragma unroll
    for (int nt = 0; nt < 16; nt++) { acc[nt][0]=acc[nt][1]=acc[nt][2]=acc[nt][3]=0.f; }

    for (int kt = 0; kt < 4; kt++) {
        // stage A [128][32] (tf32-rounded)
#pragma unroll
        for (int q = 0; q < 4; q++) {
            int f = tid + q * 256;
            int row = f >> 3, c4 = (f & 7) * 4;
            int gr = br + row;
            float4 a4 = make_float4(0.f, 0.f, 0.f, 0.f);
            if (gr < Nn) a4 = *(const float4*)&g_h[gr * HIDD + kt * 32 + c4];
            As[row][c4 + 0] = to_tf32(a4.x);
            As[row][c4 + 1] = to_tf32(a4.y);
            As[row][c4 + 2] = to_tf32(a4.z);
            As[row][c4 + 3] = to_tf32(a4.w);
        }
        // stage W [32][128] (tf32-rounded)
#pragma unroll
        for (int q = 0; q < 4; q++) {
            int f = tid + q * 256;
            int row = f >> 5, col = (f & 31) * 4;
            float4 w4 = *(const float4*)&W[(kt * 32 + row) * HIDD + col];
            Ws[row][col + 0] = to_tf32(w4.x);
            Ws[row][col + 1] = to_tf32(w4.y);
            Ws[row][col + 2] = to_tf32(w4.z);
            Ws[row][col + 3] = to_tf32(w4.w);
        }
        __syncthreads();
#pragma unroll
        for (int ks = 0; ks < 4; ks++) {
            int kb = ks * 8;
            unsigned a0 = __float_as_uint(As[r0][kb + t]);
            unsigned a1 = __float_as_uint(As[r0 + 8][kb + t]);
            unsigned a2 = __float_as_uint(As[r0][kb + t + 4]);
            unsigned a3 = __float_as_uint(As[r0 + 8][kb + t + 4]);
#pragma unroll
            for (int nt = 0; nt < 16; nt++) {
                unsigned b0 = __float_as_uint(Ws[kb + t][nt * 8 + g]);
                unsigned b1 = __float_as_uint(Ws[kb + t + 4][nt * 8 + g]);
                asm volatile(
                    "mma.sync.aligned.m16n8k8.row.col.f32.tf32.tf32.f32 "
                    "{%0,%1,%2,%3}, {%4,%5,%6,%7}, {%8,%9}, {%0,%1,%2,%3};"
                    : "+f"(acc[nt][0]), "+f"(acc[nt][1]), "+f"(acc[nt][2]), "+f"(acc[nt][3])
                    : "r"(a0), "r"(a1), "r"(a2), "r"(a3), "r"(b0), "r"(b1));
            }
        }
        __syncthreads();
    }

    // store xs: c0/c1 -> row r0, cols nt*8+2t(+1); c2/c3 -> row r0+8
    int gr0 = br + r0, gr1 = br + r0 + 8;
#pragma unroll
    for (int nt = 0; nt < 16; nt++) {
        if (gr0 < Nn) {
            float2 v = make_float2(acc[nt][0], acc[nt][1]);
            *(float2*)&g_xs[gr0 * HIDD + nt * 8 + 2 * t] = v;
        }
        if (gr1 < Nn) {
            float2 v = make_float2(acc[nt][2], acc[nt][3]);
            *(float2*)&g_xs[gr1 * HIDD + nt * 8 + 2 * t] = v;
        }
    }

    // fused a_s/a_d from accumulators: head hh covers ntiles 4hh..4hh+3
#pragma unroll
    for (int hh = 0; hh < 4; hh++) {
        float ps0 = 0.f, pd0 = 0.f, ps1 = 0.f, pd1 = 0.f;
#pragma unroll
        for (int j = 0; j < 4; j++) {
            int nt = hh * 4 + j;
            int c0 = l * HIDD + nt * 8 + 2 * t;
            float s0 = att_src[c0], s1 = att_src[c0 + 1];
            float d0 = att_dst[c0], d1 = att_dst[c0 + 1];
            ps0 += acc[nt][0] * s0 + acc[nt][1] * s1;
            ps1 += acc[nt][2] * s0 + acc[nt][3] * s1;
            pd0 += acc[nt][0] * d0 + acc[nt][1] * d1;
            pd1 += acc[nt][2] * d0 + acc[nt][3] * d1;
        }
        ps0 += __shfl_down_sync(0xffffffffu, ps0, 2, 4);
        ps0 += __shfl_down_sync(0xffffffffu, ps0, 1, 4);
        ps1 += __shfl_down_sync(0xffffffffu, ps1, 2, 4);
        ps1 += __shfl_down_sync(0xffffffffu, ps1, 1, 4);
        pd0 += __shfl_down_sync(0xffffffffu, pd0, 2, 4);
        pd0 += __shfl_down_sync(0xffffffffu, pd0, 1, 4);
        pd1 += __shfl_down_sync(0xffffffffu, pd1, 2, 4);
        pd1 += __shfl_down_sync(0xffffffffu, pd1, 1, 4);
        if (t == 0) {
            if (gr0 < Nn) { g_as[gr0 * HEADS + hh] = ps0; g_ad[gr0 * HEADS + hh] = pd0; }
            if (gr1 < Nn) { g_as[gr1 * HEADS + hh] = ps1; g_ad[gr1 * HEADS + hh] = pd1; }
        }
    }
}

// ---------------- fused edge kernel: warp per dst, single pass, no max -----
__global__ void __launch_bounds__(256) k_edge(const float* __restrict__ conv_b,
                       const float* __restrict__ gamma, const float* __restrict__ beta,
                       const float* __restrict__ mean, const float* __restrict__ var,
                       int l) {
    int warp = (blockIdx.x * blockDim.x + threadIdx.x) >> 5;
    int lane = threadIdx.x & 31;
    if (warp >= Nn) return;
    const int d = warp;
    const int h = lane >> 3;
    const int r0 = g_row[d], r1 = g_row[d + 1];
    const float base = g_ad[d * HEADS + h] + g_uv[LL * HEADS + l * HEADS + h];
    const float u = g_uv[l * HEADS + h];

    float den = 0.f;
    float ac0 = 0.f, ac1 = 0.f, ac2 = 0.f, ac3 = 0.f;

    int e = r0;
    for (; e + 3 < r1; e += 4) {
        int2 P0 = g_pack[e],     P1 = g_pack[e + 1];
        int2 P2 = g_pack[e + 2], P3 = g_pack[e + 3];
        float as0 = g_as[P0.x * HEADS + h];
        float as1 = g_as[P1.x * HEADS + h];
        float as2 = g_as[P2.x * HEADS + h];
        float as3 = g_as[P3.x * HEADS + h];
        float4 X0 = *(const float4*)&g_xs[P0.x * HIDD + lane * 4];
        float4 X1 = *(const float4*)&g_xs[P1.x * HIDD + lane * 4];
        float4 X2 = *(const float4*)&g_xs[P2.x * HIDD + lane * 4];
        float4 X3 = *(const float4*)&g_xs[P3.x * HIDD + lane * 4];
        float al0 = as0 + base + __int_as_float(P0.y) * u;
        float al1 = as1 + base + __int_as_float(P1.y) * u;
        float al2 = as2 + base + __int_as_float(P2.y) * u;
        float al3 = as3 + base + __int_as_float(P3.y) * u;
        al0 = (al0 > 0.f) ? al0 : 0.2f * al0;
        al1 = (al1 > 0.f) ? al1 : 0.2f * al1;
        al2 = (al2 > 0.f) ? al2 : 0.2f * al2;
        al3 = (al3 > 0.f) ? al3 : 0.2f * al3;
        float p0 = __expf(al0);
        float p1 = __expf(al1);
        float p2 = __expf(al2);
        float p3 = __expf(al3);
        den += (p0 + p1) + (p2 + p3);
        ac0 += p0 * X0.x + p1 * X1.x + p2 * X2.x + p3 * X3.x;
        ac1 += p0 * X0.y + p1 * X1.y + p2 * X2.y + p3 * X3.y;
        ac2 += p0 * X0.z + p1 * X1.z + p2 * X2.z + p3 * X3.z;
        ac3 += p0 * X0.w + p1 * X1.w + p2 * X2.w + p3 * X3.w;
    }
    for (; e < r1; e++) {
        int2 P0 = g_pack[e];
        float as0 = g_as[P0.x * HEADS + h];
        float4 X0 = *(const float4*)&g_xs[P0.x * HIDD + lane * 4];
        float al0 = as0 + base + __int_as_float(P0.y) * u;
        al0 = (al0 > 0.f) ? al0 : 0.2f * al0;
        float p0 = __expf(al0);
        den += p0;
        ac0 += p0 * X0.x;
        ac1 += p0 * X0.y;
        ac2 += p0 * X0.z;
        ac3 += p0 * X0.w;
    }
    float scale = 1.f / (den + 1e-16f);

    int cb = l * HIDD + lane * 4;
    float4 cb4 = *(const float4*)&conv_b[cb];
    float4 gm4 = *(const float4*)&gamma[cb];
    float4 bt4 = *(const float4*)&beta[cb];
    float4 mn4 = *(const float4*)&mean[cb];
    float4 vr4 = *(const float4*)&var[cb];
    float4 hv = *(const float4*)&g_h[d * HIDD + lane * 4];
    float o0 = (ac0 * scale + cb4.x - mn4.x) * rsqrtf(vr4.x + 1e-5f) * gm4.x + bt4.x;
    float o1 = (ac1 * scale + cb4.y - mn4.y) * rsqrtf(vr4.y + 1e-5f) * gm4.y + bt4.y;
    float o2 = (ac2 * scale + cb4.z - mn4.z) * rsqrtf(vr4.z + 1e-5f) * gm4.z + bt4.z;
    float o3 = (ac3 * scale + cb4.w - mn4.w) * rsqrtf(vr4.w + 1e-5f) * gm4.w + bt4.w;
    hv.x += fmaxf(o0, 0.f);
    hv.y += fmaxf(o1, 0.f);
    hv.z += fmaxf(o2, 0.f);
    hv.w += fmaxf(o3, 0.f);
    *(float4*)&g_h[d * HIDD + lane * 4] = hv;
}

// ---------------- pooling ---------------------------------------------------
__global__ void k_zeropool() {
    int i = blockIdx.x * blockDim.x + threadIdx.x;
    if (i < GG * HIDD) g_pooled[i] = 0.f;
    if (i < GG) g_cnt[i] = 0.f;
}

#define NPB 256
__global__ void k_pool(const int* __restrict__ batch) {
    int c = threadIdx.x;              // 128 channels
    int n0 = blockIdx.x * NPB;
    int n1 = min(n0 + NPB, Nn);
    int cur = -1; float s = 0.f; float cn = 0.f;
    for (int n = n0; n < n1; n++) {
        int g = batch[n];
        if (g != cur) {
            if (cur >= 0) {
                atomicAdd(&g_pooled[cur * HIDD + c], s);
                if (c == 0) atomicAdd(&g_cnt[cur], cn);
            }
            cur = g; s = 0.f; cn = 0.f;
        }
        s += g_h[n * HIDD + c];
        cn += 1.f;
    }
    if (cur >= 0) {
        atomicAdd(&g_pooled[cur * HIDD + c], s);
        if (c == 0) atomicAdd(&g_cnt[cur], cn);
    }
}

// ---------------- classifier head ------------------------------------------
__global__ void k_mlp1(const float* __restrict__ w1, const float* __restrict__ b1) {
    int i = blockIdx.x * blockDim.x + threadIdx.x;   // GG*64
    if (i >= GG * 64) return;
    int g = i >> 6, j = i & 63;
    float cnt = fmaxf(g_cnt[g], 1.f);
    float s = 0.f;
    for (int k = 0; k < HIDD; k++) s += g_pooled[g * HIDD + k] * w1[k * 64 + j];
    g_z[i] = fmaxf(s / cnt + b1[j], 0.f);
}

__global__ void k_mlp2(const float* __restrict__ w2, const float* __restrict__ b2,
                       float* __restrict__ out) {
    int g = threadIdx.x;
    if (g >= GG) return;
    float s = b2[0];
    for (int j = 0; j < 64; j++) s += g_z[g * 64 + j] * w2[j];
    out[g] = 1.f / (1.f + __expf(-s));
}

// ---------------- launch ----------------------------------------------------
extern "C" void kernel_launch(void* const* d_in, const int* in_sizes, int n_in,
                              void* d_out, int out_size) {
    const float* x        = (const float*)d_in[0];
    const float* ea       = (const float*)d_in[1];
    const int*   ei       = (const int*)  d_in[2];
    const int*   batch    = (const int*)  d_in[3];
    const float* enc_w    = (const float*)d_in[4];
    const float* enc_b    = (const float*)d_in[5];
    const float* eenc_w   = (const float*)d_in[6];
    const float* eenc_b   = (const float*)d_in[7];
    const float* lin_w    = (const float*)d_in[8];
    const float* att_src  = (const float*)d_in[9];
    const float* att_dst  = (const float*)d_in[10];
    const float* att_edge = (const float*)d_in[11];
    const float* lin_ew   = (const float*)d_in[12];
    const float* conv_b   = (const float*)d_in[13];
    const float* bn_gamma = (const float*)d_in[14];
    const float* bn_beta  = (const float*)d_in[15];
    const float* bn_mean  = (const float*)d_in[16];
    const float* bn_var   = (const float*)d_in[17];
    const float* w1       = (const float*)d_in[18];
    const float* b1       = (const float*)d_in[19];
    const float* w2       = (const float*)d_in[20];
    const float* b2       = (const float*)d_in[21];
    float* out = (float*)d_out;

    const int TB = 256;
    int gridNH = (Nn * HIDD + TB - 1) / TB;
    int gridE  = (Ee + TB - 1) / TB;
    int gridN  = (Nn + TB - 1) / TB;
    int gridNW = (Nn * 32 + TB - 1) / TB;

    k_enc<<<gridNH, TB>>>(x, enc_w, enc_b);
    k_uv<<<1, 256>>>(eenc_w, eenc_b, lin_ew, att_edge);

    // CSR build (by dst)
    k_hist<<<gridE, TB>>>(ei);
    k_scan1<<<NCHUNK, 256>>>();
    k_scan2<<<1, 32>>>();
    k_scan3<<<gridN, TB>>>();
    k_scatter<<<gridE, TB>>>(ei, ea);

    for (int l = 0; l < LL; l++) {
        k_gemm<<<(Nn + 127) / 128, 256>>>(lin_w + l * HIDD * HIDD, att_src, att_dst, l);
        k_edge<<<gridNW, TB>>>(conv_b, bn_gamma, bn_beta, bn_mean, bn_var, l);
    }

    k_zeropool<<<(GG * HIDD + TB - 1) / TB, TB>>>();
    k_pool<<<(Nn + NPB - 1) / NPB, 128>>>(batch);
    k_mlp1<<<(GG * 64 + TB - 1) / TB, TB>>>(w1, b1);
    k_mlp2<<<1, 64>>>(w2, b2, out);
}

// round 6
// speedup vs baseline: 1.2261x; 1.1188x over previous
#include <cuda_runtime.h>
#include <cuda_fp16.h>

#define Nn   100000
#define Ee   1600000
#define HIDD 128
#define HEADS 4
#define CH   32
#define LL   2
#define GG   64
#define NCHUNK ((Nn + 255) / 256)   // 391

// ---------------- scratch (static device globals; no allocation) -----------
__device__ __align__(16) float    g_h[Nn*HIDD];
__device__ __align__(16) __half   g_xsh[Nn*HIDD];   // fp16 xs (only consumer: k_edge)
__device__ __align__(16) float    g_as[Nn*HEADS];
__device__ __align__(16) float    g_ad[Nn*HEADS];
__device__ __align__(16) float    g_uv[2*LL*HEADS];
__device__ __align__(16) float    g_pooled[GG*HIDD];
__device__           float        g_cnt[GG];
__device__ __align__(16) float    g_z[GG*64];
// CSR by destination
__device__ __align__(16) int      g_deg[Nn];
__device__ __align__(16) int      g_row[Nn + 1];
__device__ __align__(16) int      g_cur[Nn];
__device__ __align__(16) int      g_bsum[NCHUNK];
__device__ __align__(16) int      g_boff[NCHUNK];
__device__ __align__(16) int2     g_pack[Ee];      // (src, ea bits)

__device__ __forceinline__ float to_tf32(float x) {
    unsigned u;
    asm("cvt.rna.tf32.f32 %0, %1;" : "=r"(u) : "f"(x));
    return __uint_as_float(u);
}

// ---------------- node encoder + degree zero + histogram -------------------
__global__ void k_enc(const float* __restrict__ x, const float* __restrict__ ew,
                      const float* __restrict__ eb, const int* __restrict__ ei) {
    int i = blockIdx.x * blockDim.x + threadIdx.x;
    if (i < Nn) g_deg[i] = 0;
    if (i >= Nn * HIDD) return;
    int n = i >> 7, c = i & 127;
    g_h[i] = x[n] * ew[c] + eb[c];
}

__global__ void k_hist(const int* __restrict__ ei) {
    int e = blockIdx.x * blockDim.x + threadIdx.x;
    if (e >= Ee) return;
    atomicAdd(&g_deg[ei[Ee + e]], 1);
}

// ---------------- precompute a_e coefficients u,v (rank-1 edge path) -------
__global__ void k_uv(const float* __restrict__ eenc_w, const float* __restrict__ eenc_b,
                     const float* __restrict__ lew, const float* __restrict__ att_e) {
    int tid = threadIdx.x;                 // 256 = L*H*C
    int l = tid >> 7, h = (tid >> 5) & 3, c = tid & 31;
    const float* W = lew + l * HIDD * HIDD;
    int col = h * CH + c;
    float wc = 0.f, bc = 0.f;
    for (int k = 0; k < HIDD; k++) {
        float w = W[k * HIDD + col];
        wc += eenc_w[k] * w;
        bc += eenc_b[k] * w;
    }
    float ae = att_e[l * HEADS * CH + h * CH + c];
    float uu = wc * ae, vv = bc * ae;
    for (int off = 16; off; off >>= 1) {
        uu += __shfl_down_sync(0xffffffffu, uu, off);
        vv += __shfl_down_sync(0xffffffffu, vv, off);
    }
    if (c == 0) {
        g_uv[l * HEADS + h] = uu;
        g_uv[LL * HEADS + l * HEADS + h] = vv;
    }
}

__global__ void k_scan1() {
    __shared__ int sd[256];
    int t = threadIdx.x;
    int i = blockIdx.x * 256 + t;
    int v = (i < Nn) ? g_deg[i] : 0;
    sd[t] = v;
    __syncthreads();
    for (int off = 1; off < 256; off <<= 1) {
        int x = (t >= off) ? sd[t - off] : 0;
        __syncthreads();
        sd[t] += x;
        __syncthreads();
    }
    if (i < Nn) g_row[i] = sd[t] - v;          // exclusive within chunk
    if (t == 255) g_bsum[blockIdx.x] = sd[255];
}

__global__ void k_scan2() {
    if (threadIdx.x == 0) {
        int run = 0;
        for (int b = 0; b < NCHUNK; b++) { g_boff[b] = run; run += g_bsum[b]; }
    }
}

__global__ void k_scan3() {
    int i = blockIdx.x * blockDim.x + threadIdx.x;
    if (i == 0) g_row[Nn] = Ee;
    if (i >= Nn) return;
    int r = g_row[i] + g_boff[i >> 8];
    g_row[i] = r;
    g_cur[i] = r;
}

__global__ void k_scatter(const int* __restrict__ ei, const float* __restrict__ ea) {
    int e = blockIdx.x * blockDim.x + threadIdx.x;
    if (e >= Ee) return;
    int d = ei[Ee + e];
    int pos = atomicAdd(&g_cur[d], 1);
    g_pack[pos] = make_int2(ei[e], __float_as_int(ea[e]));
}

// ---------------- xs = h @ W  via tf32 mma.sync (128-row CTA) --------------
__global__ void __launch_bounds__(256) k_gemm(const float* __restrict__ W,
                      const float* __restrict__ att_src,
                      const float* __restrict__ att_dst, int l) {
    __shared__ float As[128][36];
    __shared__ float Ws[32][132];
    int tid = threadIdx.x;
    int warp = tid >> 5, lane = tid & 31;
    int g = lane >> 2, t = lane & 3;
    int br = blockIdx.x * 128;
    int r0 = warp * 16 + g;

    float acc[16][4];
#pragma unroll
    for (int nt = 0; nt < 16; nt++) { acc[nt][0]=acc[nt][1]=acc[nt][2]=acc[nt][3]=0.f; }

    for (int kt = 0; kt < 4; kt++) {
#pragma unroll
        for (int q = 0; q < 4; q++) {
            int f = tid + q * 256;
            int row = f >> 3, c4 = (f & 7) * 4;
            int gr = br + row;
            float4 a4 = make_float4(0.f, 0.f, 0.f, 0.f);
            if (gr < Nn) a4 = *(const float4*)&g_h[gr * HIDD + kt * 32 + c4];
            As[row][c4 + 0] = to_tf32(a4.x);
            As[row][c4 + 1] = to_tf32(a4.y);
            As[row][c4 + 2] = to_tf32(a4.z);
            As[row][c4 + 3] = to_tf32(a4.w);
        }
#pragma unroll
        for (int q = 0; q < 4; q++) {
            int f = tid + q * 256;
            int row = f >> 5, col = (f & 31) * 4;
            float4 w4 = *(const float4*)&W[(kt * 32 + row) * HIDD + col];
            Ws[row][col + 0] = to_tf32(w4.x);
            Ws[row][col + 1] = to_tf32(w4.y);
            Ws[row][col + 2] = to_tf32(w4.z);
            Ws[row][col + 3] = to_tf32(w4.w);
        }
        __syncthreads();
#pragma unroll
        for (int ks = 0; ks < 4; ks++) {
            int kb = ks * 8;
            unsigned a0 = __float_as_uint(As[r0][kb + t]);
            unsigned a1 = __float_as_uint(As[r0 + 8][kb + t]);
            unsigned a2 = __float_as_uint(As[r0][kb + t + 4]);
            unsigned a3 = __float_as_uint(As[r0 + 8][kb + t + 4]);
#pragma unroll
            for (int nt = 0; nt < 16; nt++) {
                unsigned b0 = __float_as_uint(Ws[kb + t][nt * 8 + g]);
                unsigned b1 = __float_as_uint(Ws[kb + t + 4][nt * 8 + g]);
                asm volatile(
                    "mma.sync.aligned.m16n8k8.row.col.f32.tf32.tf32.f32 "
                    "{%0,%1,%2,%3}, {%4,%5,%6,%7}, {%8,%9}, {%0,%1,%2,%3};"
                    : "+f"(acc[nt][0]), "+f"(acc[nt][1]), "+f"(acc[nt][2]), "+f"(acc[nt][3])
                    : "r"(a0), "r"(a1), "r"(a2), "r"(a3), "r"(b0), "r"(b1));
            }
        }
        __syncthreads();
    }

    // store xs as fp16 pairs
    int gr0 = br + r0, gr1 = br + r0 + 8;
#pragma unroll
    for (int nt = 0; nt < 16; nt++) {
        if (gr0 < Nn)
            *(__half2*)&g_xsh[gr0 * HIDD + nt * 8 + 2 * t] = __floats2half2_rn(acc[nt][0], acc[nt][1]);
        if (gr1 < Nn)
            *(__half2*)&g_xsh[gr1 * HIDD + nt * 8 + 2 * t] = __floats2half2_rn(acc[nt][2], acc[nt][3]);
    }

    // fused a_s/a_d (fp32 accumulators): head hh covers ntiles 4hh..4hh+3
#pragma unroll
    for (int hh = 0; hh < 4; hh++) {
        float ps0 = 0.f, pd0 = 0.f, ps1 = 0.f, pd1 = 0.f;
#pragma unroll
        for (int j = 0; j < 4; j++) {
            int nt = hh * 4 + j;
            int c0 = l * HIDD + nt * 8 + 2 * t;
            float s0 = att_src[c0], s1 = att_src[c0 + 1];
            float d0 = att_dst[c0], d1 = att_dst[c0 + 1];
            ps0 += acc[nt][0] * s0 + acc[nt][1] * s1;
            ps1 += acc[nt][2] * s0 + acc[nt][3] * s1;
            pd0 += acc[nt][0] * d0 + acc[nt][1] * d1;
            pd1 += acc[nt][2] * d0 + acc[nt][3] * d1;
        }
        ps0 += __shfl_down_sync(0xffffffffu, ps0, 2, 4);
        ps0 += __shfl_down_sync(0xffffffffu, ps0, 1, 4);
        ps1 += __shfl_down_sync(0xffffffffu, ps1, 2, 4);
        ps1 += __shfl_down_sync(0xffffffffu, ps1, 1, 4);
        pd0 += __shfl_down_sync(0xffffffffu, pd0, 2, 4);
        pd0 += __shfl_down_sync(0xffffffffu, pd0, 1, 4);
        pd1 += __shfl_down_sync(0xffffffffu, pd1, 2, 4);
        pd1 += __shfl_down_sync(0xffffffffu, pd1, 1, 4);
        if (t == 0) {
            if (gr0 < Nn) { g_as[gr0 * HEADS + hh] = ps0; g_ad[gr0 * HEADS + hh] = pd0; }
            if (gr1 < Nn) { g_as[gr1 * HEADS + hh] = ps1; g_ad[gr1 * HEADS + hh] = pd1; }
        }
    }
}

// ---------------- fused edge kernel: warp per dst, fp16 gathers ------------
__device__ __forceinline__ void gath4(const __half* p, int lane,
                                      float2& f01, float2& f23) {
    uint2 q = *(const uint2*)(p + lane * 4);
    f01 = __half22float2(*(__half2*)&q.x);
    f23 = __half22float2(*(__half2*)&q.y);
}

__global__ void __launch_bounds__(128) k_edge(const float* __restrict__ conv_b,
                       const float* __restrict__ gamma, const float* __restrict__ beta,
                       const float* __restrict__ mean, const float* __restrict__ var,
                       int l) {
    int warp = (blockIdx.x * blockDim.x + threadIdx.x) >> 5;
    int lane = threadIdx.x & 31;
    if (warp >= Nn) return;
    const int d = warp;
    const int h = lane >> 3;
    const int r0 = g_row[d], r1 = g_row[d + 1];
    const float base = g_ad[d * HEADS + h] + g_uv[LL * HEADS + l * HEADS + h];
    const float u = g_uv[l * HEADS + h];

    float den = 0.f;
    float ac0 = 0.f, ac1 = 0.f, ac2 = 0.f, ac3 = 0.f;

    int e = r0;
    for (; e + 3 < r1; e += 4) {
        int2 P0 = g_pack[e],     P1 = g_pack[e + 1];
        int2 P2 = g_pack[e + 2], P3 = g_pack[e + 3];
        float as0 = g_as[P0.x * HEADS + h];
        float as1 = g_as[P1.x * HEADS + h];
        float as2 = g_as[P2.x * HEADS + h];
        float as3 = g_as[P3.x * HEADS + h];
        float2 X0a, X0b, X1a, X1b, X2a, X2b, X3a, X3b;
        gath4(&g_xsh[P0.x * HIDD], lane, X0a, X0b);
        gath4(&g_xsh[P1.x * HIDD], lane, X1a, X1b);
        gath4(&g_xsh[P2.x * HIDD], lane, X2a, X2b);
        gath4(&g_xsh[P3.x * HIDD], lane, X3a, X3b);
        float al0 = as0 + base + __int_as_float(P0.y) * u;
        float al1 = as1 + base + __int_as_float(P1.y) * u;
        float al2 = as2 + base + __int_as_float(P2.y) * u;
        float al3 = as3 + base + __int_as_float(P3.y) * u;
        al0 = (al0 > 0.f) ? al0 : 0.2f * al0;
        al1 = (al1 > 0.f) ? al1 : 0.2f * al1;
        al2 = (al2 > 0.f) ? al2 : 0.2f * al2;
        al3 = (al3 > 0.f) ? al3 : 0.2f * al3;
        float p0 = __expf(al0);
        float p1 = __expf(al1);
        float p2 = __expf(al2);
        float p3 = __expf(al3);
        den += (p0 + p1) + (p2 + p3);
        ac0 += p0 * X0a.x + p1 * X1a.x + p2 * X2a.x + p3 * X3a.x;
        ac1 += p0 * X0a.y + p1 * X1a.y + p2 * X2a.y + p3 * X3a.y;
        ac2 += p0 * X0b.x + p1 * X1b.x + p2 * X2b.x + p3 * X3b.x;
        ac3 += p0 * X0b.y + p1 * X1b.y + p2 * X2b.y + p3 * X3b.y;
    }
    for (; e < r1; e++) {
        int2 P0 = g_pack[e];
        float as0 = g_as[P0.x * HEADS + h];
        float2 X0a, X0b;
        gath4(&g_xsh[P0.x * HIDD], lane, X0a, X0b);
        float al0 = as0 + base + __int_as_float(P0.y) * u;
        al0 = (al0 > 0.f) ? al0 : 0.2f * al0;
        float p0 = __expf(al0);
        den += p0;
        ac0 += p0 * X0a.x;
        ac1 += p0 * X0a.y;
        ac2 += p0 * X0b.x;
        ac3 += p0 * X0b.y;
    }
    float scale = 1.f / (den + 1e-16f);

    int cb = l * HIDD + lane * 4;
    float4 cb4 = *(const float4*)&conv_b[cb];
    float4 gm4 = *(const float4*)&gamma[cb];
    float4 bt4 = *(const float4*)&beta[cb];
    float4 mn4 = *(const float4*)&mean[cb];
    float4 vr4 = *(const float4*)&var[cb];
    float4 hv = *(const float4*)&g_h[d * HIDD + lane * 4];
    float o0 = (ac0 * scale + cb4.x - mn4.x) * rsqrtf(vr4.x + 1e-5f) * gm4.x + bt4.x;
    float o1 = (ac1 * scale + cb4.y - mn4.y) * rsqrtf(vr4.y + 1e-5f) * gm4.y + bt4.y;
    float o2 = (ac2 * scale + cb4.z - mn4.z) * rsqrtf(vr4.z + 1e-5f) * gm4.z + bt4.z;
    float o3 = (ac3 * scale + cb4.w - mn4.w) * rsqrtf(vr4.w + 1e-5f) * gm4.w + bt4.w;
    hv.x += fmaxf(o0, 0.f);
    hv.y += fmaxf(o1, 0.f);
    hv.z += fmaxf(o2, 0.f);
    hv.w += fmaxf(o3, 0.f);
    *(float4*)&g_h[d * HIDD + lane * 4] = hv;
}

// ---------------- pooling ---------------------------------------------------
__global__ void k_zeropool() {
    int i = blockIdx.x * blockDim.x + threadIdx.x;
    if (i < GG * HIDD) g_pooled[i] = 0.f;
    if (i < GG) g_cnt[i] = 0.f;
}

#define NPB 256
__global__ void k_pool(const int* __restrict__ batch) {
    int c = threadIdx.x;              // 128 channels
    int n0 = blockIdx.x * NPB;
    int n1 = min(n0 + NPB, Nn);
    int cur = -1; float s = 0.f; float cn = 0.f;
    for (int n = n0; n < n1; n++) {
        int g = batch[n];
        if (g != cur) {
            if (cur >= 0) {
                atomicAdd(&g_pooled[cur * HIDD + c], s);
                if (c == 0) atomicAdd(&g_cnt[cur], cn);
            }
            cur = g; s = 0.f; cn = 0.f;
        }
        s += g_h[n * HIDD + c];
        cn += 1.f;
    }
    if (cur >= 0) {
        atomicAdd(&g_pooled[cur * HIDD + c], s);
        if (c == 0) atomicAdd(&g_cnt[cur], cn);
    }
}

// ---------------- classifier head ------------------------------------------
__global__ void k_mlp1(const float* __restrict__ w1, const float* __restrict__ b1) {
    int i = blockIdx.x * blockDim.x + threadIdx.x;   // GG*64
    if (i >= GG * 64) return;
    int g = i >> 6, j = i & 63;
    float cnt = fmaxf(g_cnt[g], 1.f);
    float s = 0.f;
    for (int k = 0; k < HIDD; k++) s += g_pooled[g * HIDD + k] * w1[k * 64 + j];
    g_z[i] = fmaxf(s / cnt + b1[j], 0.f);
}

__global__ void k_mlp2(const float* __restrict__ w2, const float* __restrict__ b2,
                       float* __restrict__ out) {
    int g = threadIdx.x;
    if (g >= GG) return;
    float s = b2[0];
    for (int j = 0; j < 64; j++) s += g_z[g * 64 + j] * w2[j];
    out[g] = 1.f / (1.f + __expf(-s));
}

// ---------------- launch ----------------------------------------------------
extern "C" void kernel_launch(void* const* d_in, const int* in_sizes, int n_in,
                              void* d_out, int out_size) {
    const float* x        = (const float*)d_in[0];
    const float* ea       = (const float*)d_in[1];
    const int*   ei       = (const int*)  d_in[2];
    const int*   batch    = (const int*)  d_in[3];
    const float* enc_w    = (const float*)d_in[4];
    const float* enc_b    = (const float*)d_in[5];
    const float* eenc_w   = (const float*)d_in[6];
    const float* eenc_b   = (const float*)d_in[7];
    const float* lin_w    = (const float*)d_in[8];
    const float* att_src  = (const float*)d_in[9];
    const float* att_dst  = (const float*)d_in[10];
    const float* att_edge = (const float*)d_in[11];
    const float* lin_ew   = (const float*)d_in[12];
    const float* conv_b   = (const float*)d_in[13];
    const float* bn_gamma = (const float*)d_in[14];
    const float* bn_beta  = (const float*)d_in[15];
    const float* bn_mean  = (const float*)d_in[16];
    const float* bn_var   = (const float*)d_in[17];
    const float* w1       = (const float*)d_in[18];
    const float* b1       = (const float*)d_in[19];
    const float* w2       = (const float*)d_in[20];
    const float* b2       = (const float*)d_in[21];
    float* out = (float*)d_out;

    const int TB = 256;
    int gridNH = (Nn * HIDD + TB - 1) / TB;
    int gridE  = (Ee + TB - 1) / TB;
    int gridN  = (Nn + TB - 1) / TB;
    int gridNW4 = (Nn * 32 + 127) / 128;

    k_enc<<<gridNH, TB>>>(x, enc_w, enc_b, ei);
    k_hist<<<gridE, TB>>>(ei);
    k_uv<<<1, 256>>>(eenc_w, eenc_b, lin_ew, att_edge);
    k_scan1<<<NCHUNK, 256>>>();
    k_scan2<<<1, 32>>>();
    k_scan3<<<gridN, TB>>>();
    k_scatter<<<gridE, TB>>>(ei, ea);

    for (int l = 0; l < LL; l++) {
        k_gemm<<<(Nn + 127) / 128, 256>>>(lin_w + l * HIDD * HIDD, att_src, att_dst, l);
        k_edge<<<gridNW4, 128>>>(conv_b, bn_gamma, bn_beta, bn_mean, bn_var, l);
    }

    k_zeropool<<<(GG * HIDD + TB - 1) / TB, TB>>>();
    k_pool<<<(Nn + NPB - 1) / NPB, 128>>>(batch);
    k_mlp1<<<(GG * 64 + TB - 1) / TB, TB>>>(w1, b1);
    k_mlp2<<<1, 64>>>(w2, b2, out);
}